// round 3
// baseline (speedup 1.0000x reference)
#include <cuda_runtime.h>
#include <mma.h>
#include <cstdint>

using namespace nvcuda;

#define HID   1024
#define BATCH 64
#define SEQ   256
#define NGATE 4096
#define NCTA  128
#define WHS_LD 1028

__device__ float g_xg[(size_t)BATCH * SEQ * NGATE];   // [b*SEQ+t][g*HID+k]
__device__ float g_h[4][BATCH * HID];                 // h ring (slot = t&3)
__device__ int   g_cnt[SEQ + 1];

__device__ __forceinline__ void cp16(void* s, const void* g) {
    uint32_t sa = (uint32_t)__cvta_generic_to_shared(s);
    asm volatile("cp.async.cg.shared.global [%0], [%1], 16;\n" :: "r"(sa), "l"(g));
}
__device__ __forceinline__ void cp_commit() { asm volatile("cp.async.commit_group;\n"); }
template<int N> __device__ __forceinline__ void cp_wait() {
    asm volatile("cp.async.wait_group %0;\n" :: "n"(N));
}
__device__ __forceinline__ float sigm(float x) { return 1.0f / (1.0f + __expf(-x)); }

// ------------------------------------------------------------------ init
__global__ void init_kernel(const float* __restrict__ h0) {
    int idx = blockIdx.x * blockDim.x + threadIdx.x;
    int tot = gridDim.x * blockDim.x;
    for (int i = idx; i < BATCH * HID; i += tot) g_h[0][i] = h0[i];
    if (blockIdx.x == 0)
        for (int i = threadIdx.x; i <= SEQ; i += blockDim.x)
            g_cnt[i] = (i == 0) ? NCTA : 0;
}

// ------------------------------------------------------------------ phase A
#define BK 32
#define ASMEM (2 * 3 * 128 * 36 * 4)
__global__ void __launch_bounds__(256) gemm_xg_kernel(const float* __restrict__ x,
                                                      const float* __restrict__ Wx) {
    extern __shared__ float sm[];
    float* As = sm;                   // [3][128][36]
    float* Bs = sm + 3 * 128 * 36;    // [3][128][36]
    const int tid = threadIdx.x;
    const int wid = tid >> 5;
    const int wm = wid & 3, wn = wid >> 2;
    const int tm = blockIdx.y * 128;
    const int tn = blockIdx.x * 128;

    wmma::fragment<wmma::accumulator, 16, 16, 8, float> acc[2][4];
    #pragma unroll
    for (int i = 0; i < 2; i++)
        #pragma unroll
        for (int j = 0; j < 4; j++) wmma::fill_fragment(acc[i][j], 0.0f);

    auto issue = [&](int kt) {
        int st = kt % 3;
        int kk = kt * BK;
        float* a = As + st * 128 * 36;
        float* b = Bs + st * 128 * 36;
        #pragma unroll
        for (int i = 0; i < 4; i++) {
            int li = tid + i * 256;  // 0..1023
            int r = li >> 3, sg = li & 7;
            cp16(a + r * 36 + sg * 4, x  + (size_t)(tm + r) * HID + kk + sg * 4);
            cp16(b + r * 36 + sg * 4, Wx + (size_t)(tn + r) * HID + kk + sg * 4);
        }
    };
    issue(0); cp_commit();
    issue(1); cp_commit();

    for (int kt = 0; kt < HID / BK; kt++) {
        cp_wait<1>();
        __syncthreads();
        const int st = kt % 3;
        const float* a = As + st * 128 * 36;
        const float* b = Bs + st * 128 * 36;
        #pragma unroll
        for (int ks = 0; ks < BK / 8; ks++) {
            wmma::fragment<wmma::matrix_a, 16, 16, 8, wmma::precision::tf32, wmma::row_major> af[2];
            wmma::fragment<wmma::matrix_b, 16, 16, 8, wmma::precision::tf32, wmma::col_major> bf[4];
            #pragma unroll
            for (int i = 0; i < 2; i++)
                wmma::load_matrix_sync(af[i], a + (wm * 32 + i * 16) * 36 + ks * 8, 36);
            #pragma unroll
            for (int j = 0; j < 4; j++)
                wmma::load_matrix_sync(bf[j], b + (wn * 64 + j * 16) * 36 + ks * 8, 36);
            #pragma unroll
            for (int i = 0; i < 2; i++)
                #pragma unroll
                for (int j = 0; j < 4; j++)
                    wmma::mma_sync(acc[i][j], af[i], bf[j], acc[i][j]);
        }
        if (kt + 2 < HID / BK) issue(kt + 2);
        cp_commit();
    }
    #pragma unroll
    for (int i = 0; i < 2; i++)
        #pragma unroll
        for (int j = 0; j < 4; j++) {
            size_t r = tm + wm * 32 + i * 16;
            size_t n = tn + wn * 64 + j * 16;
            wmma::store_matrix_sync(g_xg + r * NGATE + n, acc[i][j], NGATE, wmma::mem_row_major);
        }
}

// ------------------------------------------------------------------ phase B (persistent)
#define BSMEM ((32 * WHS_LD + 3 * 64 * 68 + 64 * 36 + 8 * 65 + 32 + 24) * 4)
__global__ void __launch_bounds__(256) lstm_kernel(const float* __restrict__ Wh,
                                                   const float* __restrict__ c0,
                                                   const float* __restrict__ bx,
                                                   const float* __restrict__ bh,
                                                   const float* __restrict__ peep,
                                                   const float* __restrict__ bgate,
                                                   float* __restrict__ out) {
    extern __shared__ float sm[];
    float* Whs = sm;                      // [32][WHS_LD]
    float* hAs = Whs + 32 * WHS_LD;       // [3][64][68]
    float* hgS = hAs + 3 * 64 * 68;       // [64][36]
    float* cS  = hgS + 64 * 36;           // [8][65]
    float* cb  = cS + 8 * 65;             // [32]
    float* ps  = cb + 32;                 // [24]

    const int tid = threadIdx.x;
    const int wid = tid >> 5;
    const int wb = wid & 3, wn = wid >> 2;
    const int k0 = blockIdx.x * 8;

    // one-time staging of this CTA's Wh slice (32 rows x 1024), tf32-rounded
    #pragma unroll 4
    for (int i = 0; i < 32; i++) {
        int li = tid + i * 256;           // float4 idx 0..8191
        int n = li >> 8, sg = li & 255;
        int g = n >> 3, kl = n & 7;
        const float4 v = *(const float4*)(Wh + ((size_t)(g * HID + k0 + kl)) * HID + sg * 4);
        float* d = Whs + n * WHS_LD + sg * 4;
        d[0] = wmma::__float_to_tf32(v.x);
        d[1] = wmma::__float_to_tf32(v.y);
        d[2] = wmma::__float_to_tf32(v.z);
        d[3] = wmma::__float_to_tf32(v.w);
    }
    if (tid < 32) {
        int g = tid >> 3, kl = tid & 7;
        cb[tid] = bx[g * HID + k0 + kl] + bh[g * HID + k0 + kl] + bgate[g * HID + k0 + kl];
    }
    if (tid < 24) ps[tid] = peep[(tid >> 3) * HID + k0 + (tid & 7)];
    #pragma unroll
    for (int rep = 0; rep < 2; rep++) {
        int p = tid + rep * 256;
        int b = p >> 3, kl = p & 7;
        cS[kl * 65 + b] = c0[(size_t)b * HID + k0 + kl];
    }
    __syncthreads();

    for (int t = 0; t < SEQ; t++) {
        if (tid == 0) {
            volatile int* c = &g_cnt[t];
            while (*c < NCTA) __nanosleep(40);
        }
        __syncthreads();

        const float* hsrc = g_h[t & 3];
        auto issueH = [&](int kc) {
            float* dst = hAs + (kc % 3) * 64 * 68;
            #pragma unroll
            for (int i = 0; i < 4; i++) {
                int li = tid + i * 256;   // 0..1023
                int b = li >> 4, sg = li & 15;
                cp16(dst + b * 68 + sg * 4, hsrc + (size_t)b * HID + kc * 64 + sg * 4);
            }
        };
        issueH(0); cp_commit();
        issueH(1); cp_commit();

        wmma::fragment<wmma::accumulator, 16, 16, 8, float> acc0, acc1;
        wmma::fill_fragment(acc0, 0.0f);
        wmma::fill_fragment(acc1, 0.0f);

        for (int kc = 0; kc < 16; kc++) {
            cp_wait<1>();
            __syncthreads();
            const float* a = hAs + (kc % 3) * 64 * 68;
            #pragma unroll
            for (int ks = 0; ks < 8; ks++) {
                wmma::fragment<wmma::matrix_a, 16, 16, 8, wmma::precision::tf32, wmma::row_major> af;
                wmma::fragment<wmma::matrix_b, 16, 16, 8, wmma::precision::tf32, wmma::col_major> bf;
                wmma::load_matrix_sync(af, a + (wb * 16) * 68 + ks * 8, 68);
                wmma::load_matrix_sync(bf, Whs + (wn * 16) * WHS_LD + kc * 64 + ks * 8, WHS_LD);
                if (ks & 1) wmma::mma_sync(acc1, af, bf, acc1);
                else        wmma::mma_sync(acc0, af, bf, acc0);
            }
            if (kc + 2 < 16) issueH(kc + 2);
            cp_commit();
        }
        #pragma unroll
        for (int e = 0; e < acc0.num_elements; e++) acc0.x[e] += acc1.x[e];
        wmma::store_matrix_sync(hgS + (wb * 16) * 36 + wn * 16, acc0, 36, wmma::mem_row_major);
        __syncthreads();

        float* hdst = g_h[(t + 1) & 3];
        #pragma unroll
        for (int rep = 0; rep < 2; rep++) {
            int p = tid + rep * 256;
            int b = p >> 3, kl = p & 7;
            const float* xr = g_xg + (size_t)(b * SEQ + t) * NGATE + k0 + kl;
            float c = cS[kl * 65 + b];
            float pi = xr[0]        + hgS[b * 36 +      kl] + ps[kl]      * c + cb[kl];
            float pf = xr[HID]      + hgS[b * 36 +  8 + kl] + ps[8 + kl]  * c + cb[8 + kl];
            float pc = xr[2 * HID]  + hgS[b * 36 + 16 + kl]                   + cb[16 + kl];
            float po = xr[3 * HID]  + hgS[b * 36 + 24 + kl]                   + cb[24 + kl];
            float cn = sigm(pf) * c + sigm(pi) + tanhf(pc);
            float hn = sigm(po + ps[16 + kl] * cn) * tanhf(cn);
            cS[kl * 65 + b] = cn;
            hdst[(size_t)b * HID + k0 + kl] = hn;
            out[(size_t)(b * SEQ + t) * HID + k0 + kl] = hn;
        }
        __threadfence();
        __syncthreads();
        if (tid == 0) atomicAdd(&g_cnt[t + 1], 1);
    }
}

extern "C" void kernel_launch(void* const* d_in, const int* in_sizes, int n_in,
                              void* d_out, int out_size) {
    const float* x     = (const float*)d_in[0];
    const float* h0    = (const float*)d_in[1];
    const float* c0    = (const float*)d_in[2];
    const float* Wx    = (const float*)d_in[3];
    const float* bx    = (const float*)d_in[4];
    const float* Wh    = (const float*)d_in[5];
    const float* bh    = (const float*)d_in[6];
    const float* peep  = (const float*)d_in[7];
    const float* bgate = (const float*)d_in[8];
    float* out = (float*)d_out;

    cudaFuncSetAttribute(gemm_xg_kernel, cudaFuncAttributeMaxDynamicSharedMemorySize, ASMEM);
    cudaFuncSetAttribute(lstm_kernel, cudaFuncAttributeMaxDynamicSharedMemorySize, BSMEM);

    init_kernel<<<256, 256>>>(h0);
    gemm_xg_kernel<<<dim3(32, 128), 256, ASMEM>>>(x, Wx);
    lstm_kernel<<<NCTA, 256, BSMEM>>>(Wh, c0, bx, bh, peep, bgate, out);
}

// round 4
// speedup vs baseline: 1.0051x; 1.0051x over previous
#include <cuda_runtime.h>
#include <mma.h>
#include <cstdint>

using namespace nvcuda;

#define HID   1024
#define BATCH 64
#define SEQ   256
#define NGATE 4096
#define NCTA  128
#define WHS_LD 1028

__device__ float g_xg[(size_t)BATCH * SEQ * NGATE];   // [b*SEQ+t][g*HID+k]
__device__ float g_h[4][BATCH * HID];                 // h ring (slot = t&3)
__device__ int   g_cnt[SEQ + 1];

__device__ __forceinline__ void cp16(void* s, const void* g) {
    uint32_t sa = (uint32_t)__cvta_generic_to_shared(s);
    asm volatile("cp.async.cg.shared.global [%0], [%1], 16;\n" :: "r"(sa), "l"(g));
}
__device__ __forceinline__ void cp_commit() { asm volatile("cp.async.commit_group;\n"); }
template<int N> __device__ __forceinline__ void cp_wait() {
    asm volatile("cp.async.wait_group %0;\n" :: "n"(N));
}
__device__ __forceinline__ float sigm(float x) { return 1.0f / (1.0f + __expf(-x)); }

// ------------------------------------------------------------------ phase A
// xg GEMM (M=16384, N=4096, K=1024), tf32 wmma, 128x128x32 tiles, 3-stage cp.async.
// CTA (0,0) additionally performs the init work (h0 copy + counter reset).
#define BK 32
#define ASMEM (2 * 3 * 128 * 36 * 4)
__global__ void __launch_bounds__(256, 2) gemm_xg_kernel(const float* __restrict__ x,
                                                         const float* __restrict__ Wx,
                                                         const float* __restrict__ h0) {
    extern __shared__ float sm[];
    float* As = sm;                   // [3][128][36]
    float* Bs = sm + 3 * 128 * 36;    // [3][128][36]
    const int tid = threadIdx.x;
    const int wid = tid >> 5;
    const int wm = wid & 3, wn = wid >> 2;
    const int tm = blockIdx.y * 128;
    const int tn = blockIdx.x * 128;

    if (blockIdx.x == 0 && blockIdx.y == 0) {
        // fold init: copy h0 into ring slot 0, reset per-step counters
        for (int i = tid; i < BATCH * HID; i += 256) g_h[0][i] = h0[i];
        for (int i = tid; i <= SEQ; i += 256) g_cnt[i] = (i == 0) ? NCTA : 0;
    }

    wmma::fragment<wmma::accumulator, 16, 16, 8, float> acc[2][4];
    #pragma unroll
    for (int i = 0; i < 2; i++)
        #pragma unroll
        for (int j = 0; j < 4; j++) wmma::fill_fragment(acc[i][j], 0.0f);

    auto issue = [&](int kt) {
        int st = kt % 3;
        int kk = kt * BK;
        float* a = As + st * 128 * 36;
        float* b = Bs + st * 128 * 36;
        #pragma unroll
        for (int i = 0; i < 4; i++) {
            int li = tid + i * 256;  // 0..1023
            int r = li >> 3, sg = li & 7;
            cp16(a + r * 36 + sg * 4, x  + (size_t)(tm + r) * HID + kk + sg * 4);
            cp16(b + r * 36 + sg * 4, Wx + (size_t)(tn + r) * HID + kk + sg * 4);
        }
    };
    issue(0); cp_commit();
    issue(1); cp_commit();

    for (int kt = 0; kt < HID / BK; kt++) {
        cp_wait<1>();
        __syncthreads();
        const int st = kt % 3;
        const float* a = As + st * 128 * 36;
        const float* b = Bs + st * 128 * 36;
        #pragma unroll
        for (int ks = 0; ks < BK / 8; ks++) {
            wmma::fragment<wmma::matrix_a, 16, 16, 8, wmma::precision::tf32, wmma::row_major> af[2];
            wmma::fragment<wmma::matrix_b, 16, 16, 8, wmma::precision::tf32, wmma::col_major> bf[4];
            #pragma unroll
            for (int i = 0; i < 2; i++)
                wmma::load_matrix_sync(af[i], a + (wm * 32 + i * 16) * 36 + ks * 8, 36);
            #pragma unroll
            for (int j = 0; j < 4; j++)
                wmma::load_matrix_sync(bf[j], b + (wn * 64 + j * 16) * 36 + ks * 8, 36);
            #pragma unroll
            for (int i = 0; i < 2; i++)
                #pragma unroll
                for (int j = 0; j < 4; j++)
                    wmma::mma_sync(acc[i][j], af[i], bf[j], acc[i][j]);
        }
        if (kt + 2 < HID / BK) issue(kt + 2);
        cp_commit();
    }
    #pragma unroll
    for (int i = 0; i < 2; i++)
        #pragma unroll
        for (int j = 0; j < 4; j++) {
            size_t r = tm + wm * 32 + i * 16;
            size_t n = tn + wn * 64 + j * 16;
            wmma::store_matrix_sync(g_xg + r * NGATE + n, acc[i][j], NGATE, wmma::mem_row_major);
        }
}

// ------------------------------------------------------------------ phase B (persistent)
#define BSMEM ((32 * WHS_LD + 3 * 64 * 68 + 64 * 36 + 8 * 65 + 32 + 24) * 4)
__global__ void __launch_bounds__(256) lstm_kernel(const float* __restrict__ Wh,
                                                   const float* __restrict__ c0,
                                                   const float* __restrict__ bx,
                                                   const float* __restrict__ bh,
                                                   const float* __restrict__ peep,
                                                   const float* __restrict__ bgate,
                                                   float* __restrict__ out) {
    extern __shared__ float sm[];
    float* Whs = sm;                      // [32][WHS_LD]
    float* hAs = Whs + 32 * WHS_LD;       // [3][64][68]
    float* hgS = hAs + 3 * 64 * 68;       // [64][36]
    float* cS  = hgS + 64 * 36;           // [8][65]
    float* cb  = cS + 8 * 65;             // [32]
    float* ps  = cb + 32;                 // [24]

    const int tid = threadIdx.x;
    const int wid = tid >> 5;
    const int wb = wid & 3, wn = wid >> 2;
    const int k0 = blockIdx.x * 8;

    // one-time staging of this CTA's Wh slice (32 rows x 1024), tf32-rounded
    #pragma unroll 4
    for (int i = 0; i < 32; i++) {
        int li = tid + i * 256;           // float4 idx 0..8191
        int n = li >> 8, sg = li & 255;
        int g = n >> 3, kl = n & 7;
        const float4 v = *(const float4*)(Wh + ((size_t)(g * HID + k0 + kl)) * HID + sg * 4);
        float* d = Whs + n * WHS_LD + sg * 4;
        d[0] = wmma::__float_to_tf32(v.x);
        d[1] = wmma::__float_to_tf32(v.y);
        d[2] = wmma::__float_to_tf32(v.z);
        d[3] = wmma::__float_to_tf32(v.w);
    }
    if (tid < 32) {
        int g = tid >> 3, kl = tid & 7;
        cb[tid] = bx[g * HID + k0 + kl] + bh[g * HID + k0 + kl] + bgate[g * HID + k0 + kl];
    }
    if (tid < 24) ps[tid] = peep[(tid >> 3) * HID + k0 + (tid & 7)];
    #pragma unroll
    for (int rep = 0; rep < 2; rep++) {
        int p = tid + rep * 256;
        int b = p >> 3, kl = p & 7;
        cS[kl * 65 + b] = c0[(size_t)b * HID + k0 + kl];
    }
    __syncthreads();

    for (int t = 0; t < SEQ; t++) {
        // prefetch this step's input-gate preactivations (independent of h_t)
        float xi[2][4];
        #pragma unroll
        for (int rep = 0; rep < 2; rep++) {
            int p = tid + rep * 256;
            int b = p >> 3, kl = p & 7;
            const float* xr = g_xg + (size_t)(b * SEQ + t) * NGATE + k0 + kl;
            xi[rep][0] = __ldg(xr);
            xi[rep][1] = __ldg(xr + HID);
            xi[rep][2] = __ldg(xr + 2 * HID);
            xi[rep][3] = __ldg(xr + 3 * HID);
        }

        // wait for all producers of h_t (acquire)
        if (tid == 0) {
            int v;
            while (true) {
                asm volatile("ld.global.acquire.gpu.s32 %0, [%1];"
                             : "=r"(v) : "l"(&g_cnt[t]) : "memory");
                if (v >= NCTA) break;
                __nanosleep(32);
            }
        }
        __syncthreads();

        const float* hsrc = g_h[t & 3];
        auto issueH = [&](int kc) {
            float* dst = hAs + (kc % 3) * 64 * 68;
            #pragma unroll
            for (int i = 0; i < 4; i++) {
                int li = tid + i * 256;   // 0..1023
                int b = li >> 4, sg = li & 15;
                cp16(dst + b * 68 + sg * 4, hsrc + (size_t)b * HID + kc * 64 + sg * 4);
            }
        };
        issueH(0); cp_commit();
        issueH(1); cp_commit();

        wmma::fragment<wmma::accumulator, 16, 16, 8, float> acc0, acc1;
        wmma::fill_fragment(acc0, 0.0f);
        wmma::fill_fragment(acc1, 0.0f);

        for (int kc = 0; kc < 16; kc++) {
            cp_wait<1>();
            __syncthreads();
            const float* a = hAs + (kc % 3) * 64 * 68;
            #pragma unroll
            for (int ks = 0; ks < 8; ks++) {
                wmma::fragment<wmma::matrix_a, 16, 16, 8, wmma::precision::tf32, wmma::row_major> af;
                wmma::fragment<wmma::matrix_b, 16, 16, 8, wmma::precision::tf32, wmma::col_major> bf;
                wmma::load_matrix_sync(af, a + (wb * 16) * 68 + ks * 8, 68);
                wmma::load_matrix_sync(bf, Whs + (wn * 16) * WHS_LD + kc * 64 + ks * 8, WHS_LD);
                if (ks & 1) wmma::mma_sync(acc1, af, bf, acc1);
                else        wmma::mma_sync(acc0, af, bf, acc0);
            }
            if (kc + 2 < 16) issueH(kc + 2);
            cp_commit();
        }
        #pragma unroll
        for (int e = 0; e < acc0.num_elements; e++) acc0.x[e] += acc1.x[e];
        wmma::store_matrix_sync(hgS + (wb * 16) * 36 + wn * 16, acc0, 36, wmma::mem_row_major);
        __syncthreads();

        float* hdst = g_h[(t + 1) & 3];
        #pragma unroll
        for (int rep = 0; rep < 2; rep++) {
            int p = tid + rep * 256;
            int b = p >> 3, kl = p & 7;
            float c = cS[kl * 65 + b];
            float pi = xi[rep][0] + hgS[b * 36 +      kl] + ps[kl]     * c + cb[kl];
            float pf = xi[rep][1] + hgS[b * 36 +  8 + kl] + ps[8 + kl] * c + cb[8 + kl];
            float pc = xi[rep][2] + hgS[b * 36 + 16 + kl]                  + cb[16 + kl];
            float po = xi[rep][3] + hgS[b * 36 + 24 + kl]                  + cb[24 + kl];
            float cn = sigm(pf) * c + sigm(pi) + tanhf(pc);
            float hn = sigm(po + ps[16 + kl] * cn) * tanhf(cn);
            cS[kl * 65 + b] = cn;
            hdst[(size_t)b * HID + k0 + kl] = hn;
            out[(size_t)(b * SEQ + t) * HID + k0 + kl] = hn;
        }
        __syncthreads();                    // all writes happen-before tid0's release
        if (tid == 0) {
            __threadfence();
            atomicAdd(&g_cnt[t + 1], 1);    // release arrival
        }
    }
}

extern "C" void kernel_launch(void* const* d_in, const int* in_sizes, int n_in,
                              void* d_out, int out_size) {
    const float* x     = (const float*)d_in[0];
    const float* h0    = (const float*)d_in[1];
    const float* c0    = (const float*)d_in[2];
    const float* Wx    = (const float*)d_in[3];
    const float* bx    = (const float*)d_in[4];
    const float* Wh    = (const float*)d_in[5];
    const float* bh    = (const float*)d_in[6];
    const float* peep  = (const float*)d_in[7];
    const float* bgate = (const float*)d_in[8];
    float* out = (float*)d_out;

    cudaFuncSetAttribute(gemm_xg_kernel, cudaFuncAttributeMaxDynamicSharedMemorySize, ASMEM);
    cudaFuncSetAttribute(lstm_kernel, cudaFuncAttributeMaxDynamicSharedMemorySize, BSMEM);

    gemm_xg_kernel<<<dim3(32, 128), 256, ASMEM>>>(x, Wx, h0);
    lstm_kernel<<<NCTA, 256, BSMEM>>>(Wh, c0, bx, bh, peep, bgate, out);
}